// round 1
// baseline (speedup 1.0000x reference)
#include <cuda_runtime.h>
#include <cstdint>

#define BSZ 32
#define HWPIX 409600
#define NPIX 13107200
#define NGRP 3276800          // NPIX/4
#define HW4 102400            // HWPIX/4
#define NB1 8192
#define NB2 4096
#define CAND_CAP (1u<<22)     // 4M floats = 16MB
#define MARGIN 150000LL       // rank-margin for sampled bracket (~14 sigma)

// -------- device scratch (static: no allocations allowed) --------
__device__ float4 g_scratch[NGRP];          // row_neg per pixel (se or -1)
__device__ float  g_cand[CAND_CAP];         // bracket candidates
__device__ unsigned int g_hist[NB1];        // sampled coarse histogram
__device__ unsigned int g_fcnt[NB2];        // fine histogram counts
__device__ float        g_fsum[NB2];        // fine histogram value sums
__device__ double g_pos_loss;
__device__ double g_pos_w;
__device__ double g_sum_above;
__device__ unsigned int g_sumPos;
__device__ unsigned int g_cnt_above;
__device__ unsigned int g_cand_n;
__device__ int g_blo, g_bhi, g_shift;
__device__ long long g_K;

// ---------------------------------------------------------------
__global__ void k_init() {
  int t = blockIdx.x * blockDim.x + threadIdx.x;
  int n = gridDim.x * blockDim.x;
  for (int i = t; i < NB1; i += n) g_hist[i] = 0u;
  for (int i = t; i < NB2; i += n) { g_fcnt[i] = 0u; g_fsum[i] = 0.f; }
  if (t == 0) {
    g_pos_loss = 0.0; g_pos_w = 0.0; g_sum_above = 0.0;
    g_sumPos = 0u; g_cnt_above = 0u; g_cand_n = 0u;
  }
}

// ---------------------------------------------------------------
__device__ __forceinline__ float rowval(float p0, float p1, float t0, float t1,
                                        float w, float& pl, float& pw,
                                        unsigned& np, bool samp, unsigned* sh) {
  float d0 = p0 - t0, d1 = p1 - t1;
  float se = fmaf(d0, d0, d1 * d1);
  if (w > 0.f) { pl = fmaf(se, w, pl); pw += w; np++; return -1.f; }
  if (samp) atomicAdd(&sh[__float_as_uint(se) >> 19], 1u);
  return se;
}

__global__ void __launch_bounds__(256) k_main(const float4* __restrict__ pr,
                                              const float4* __restrict__ vm,
                                              const float4* __restrict__ wt) {
  __shared__ unsigned sh[NB1];
  for (int i = threadIdx.x; i < NB1; i += 256) sh[i] = 0u;
  __syncthreads();
  float pl = 0.f, pw = 0.f; unsigned np = 0u;
  int stride = gridDim.x * blockDim.x;
  for (int g = blockIdx.x * blockDim.x + threadIdx.x; g < NGRP; g += stride) {
    int b = g / HW4;                 // batch index
    int base = g + b * HW4;          // float4 index of channel-0 pixel group
    float4 p0 = pr[base], p1 = pr[base + HW4];
    float4 t0 = vm[base], t1 = vm[base + HW4];
    float4 w = wt[g];
    bool samp = ((g & 15) == 0);     // every 64th pixel (lane x only)
    float4 o;
    o.x = rowval(p0.x, p1.x, t0.x, t1.x, w.x, pl, pw, np, samp, sh);
    o.y = rowval(p0.y, p1.y, t0.y, t1.y, w.y, pl, pw, np, false, sh);
    o.z = rowval(p0.z, p1.z, t0.z, t1.z, w.z, pl, pw, np, false, sh);
    o.w = rowval(p0.w, p1.w, t0.w, t1.w, w.w, pl, pw, np, false, sh);
    g_scratch[g] = o;
  }
  for (int o = 16; o; o >>= 1) {
    pl += __shfl_down_sync(0xffffffffu, pl, o);
    pw += __shfl_down_sync(0xffffffffu, pw, o);
    np += __shfl_down_sync(0xffffffffu, np, o);
  }
  if ((threadIdx.x & 31u) == 0u) {
    if (pl != 0.f) atomicAdd(&g_pos_loss, (double)pl);
    if (pw != 0.f) atomicAdd(&g_pos_w, (double)pw);
    if (np) atomicAdd(&g_sumPos, np);
  }
  __syncthreads();
  for (int i = threadIdx.x; i < NB1; i += 256) {
    unsigned c = sh[i];
    if (c) atomicAdd(&g_hist[i], c);
  }
}

// ---------------------------------------------------------------
// From sampled histogram find bracket bins [blo, bhi] containing the
// K-th largest negative with wide margin. 1 block, 256 threads.
__global__ void k_thresh() {
  __shared__ unsigned csum[256];
  __shared__ int s_blo, s_bhi;
  __shared__ long long sK;
  int t = threadIdx.x;
  if (t == 0) {
    long long sp = (long long)g_sumPos;
    long long K = 3 * sp;
    long long sn = (long long)NPIX - sp;
    if (K > sn) K = sn;
    sK = K; g_K = K;
    s_blo = 0; s_bhi = NB1;
  }
  __syncthreads();
  long long K = sK;
  int top = NB1 - 32 * t;            // chunk t: bins [top-32, top), top-down
  unsigned cs[32]; unsigned s = 0;
#pragma unroll
  for (int j = 0; j < 32; j++) { cs[j] = g_hist[top - 1 - j]; s += cs[j]; }
  csum[t] = s;
  __syncthreads();
  for (int off = 1; off < 256; off <<= 1) {
    unsigned v = (t >= off) ? csum[t - off] : 0u;
    __syncthreads();
    csum[t] += v;
    __syncthreads();
  }
  unsigned long long run = (unsigned long long)csum[t] - s;  // samples above chunk
#pragma unroll
  for (int j = 0; j < 32; j++) {
    int b = top - 1 - j;
    long long above = (long long)run * 64;   // est. count with bin >= b+1
    run += cs[j];
    long long atb = (long long)run * 64;     // est. count with bin >= b
    if (atb >= K + MARGIN) atomicMax(&s_blo, b);
    if (above <= K - MARGIN) atomicMin(&s_bhi, b);
  }
  __syncthreads();
  if (t == 0) {
    int blo = s_blo;
    int bhi = s_bhi;
    if (bhi >= NB1) bhi = NB1 - 1;
    if (bhi < blo) bhi = blo;
    int range = bhi - blo + 1;
    int shift = 0;
    while ((((long long)range) << 12) >> shift > NB2) shift++;
    g_blo = blo; g_bhi = bhi; g_shift = shift;
  }
}

// ---------------------------------------------------------------
// Pass over scratch: exact sum/count above bracket, collect candidates.
__global__ void __launch_bounds__(256) k_collect() {
  int blo = g_blo, bhi = g_bhi;
  float sa = 0.f; unsigned ca = 0u;
  int stride = gridDim.x * blockDim.x;
  for (int g = blockIdx.x * blockDim.x + threadIdx.x; g < NGRP; g += stride) {
    float4 v4 = g_scratch[g];
    float vv[4] = {v4.x, v4.y, v4.z, v4.w};
#pragma unroll
    for (int j = 0; j < 4; j++) {
      float v = vv[j];
      if (v >= 0.f) {
        int bin = (int)(__float_as_uint(v) >> 19);
        if (bin > bhi) { sa += v; ca++; }
        else if (bin >= blo) {
          unsigned mask = __activemask();
          unsigned lane = threadIdx.x & 31u;
          unsigned leader = __ffs(mask) - 1u;
          unsigned rnk = __popc(mask & ((1u << lane) - 1u));
          unsigned base = 0u;
          if (lane == leader) base = atomicAdd(&g_cand_n, (unsigned)__popc(mask));
          base = __shfl_sync(mask, base, leader);
          unsigned idx = base + rnk;
          if (idx < CAND_CAP) g_cand[idx] = v;
        }
      }
    }
  }
  for (int o = 16; o; o >>= 1) {
    sa += __shfl_down_sync(0xffffffffu, sa, o);
    ca += __shfl_down_sync(0xffffffffu, ca, o);
  }
  if ((threadIdx.x & 31u) == 0u) {
    if (sa != 0.f) atomicAdd(&g_sum_above, (double)sa);
    if (ca) atomicAdd(&g_cnt_above, ca);
  }
}

// ---------------------------------------------------------------
// Fine histogram of candidates (counts + sums), privatized in shared.
__global__ void __launch_bounds__(256) k_fine() {
  __shared__ unsigned scnt[NB2];
  __shared__ float ssum[NB2];
  for (int i = threadIdx.x; i < NB2; i += 256) { scnt[i] = 0u; ssum[i] = 0.f; }
  __syncthreads();
  unsigned nc = g_cand_n; if (nc > CAND_CAP) nc = CAND_CAP;
  unsigned base = ((unsigned)g_blo) << 12;
  int shift = g_shift;
  unsigned stride = gridDim.x * blockDim.x;
  for (unsigned i = blockIdx.x * blockDim.x + threadIdx.x; i < nc; i += stride) {
    float v = g_cand[i];
    unsigned key = ((__float_as_uint(v) >> 7) - base) >> shift;
    if (key >= NB2) key = NB2 - 1;
    atomicAdd(&scnt[key], 1u);
    atomicAdd(&ssum[key], v);
  }
  __syncthreads();
  for (int i = threadIdx.x; i < NB2; i += 256) {
    unsigned c = scnt[i];
    if (c) { atomicAdd(&g_fcnt[i], c); atomicAdd(&g_fsum[i], ssum[i]); }
  }
}

// ---------------------------------------------------------------
// Scan fine histogram top-down, take top-r with bin-mean interpolation,
// finalize loss. 1 block, 256 threads.
__global__ void k_final(float* out) {
  __shared__ unsigned csum[256];
  __shared__ double red[256];
  int t = threadIdx.x;
  long long K = g_K;
  long long r = K - (long long)g_cnt_above;
  if (r < 0) r = 0;
  int top = NB2 - 16 * t;
  unsigned cs[16]; float fs[16]; unsigned s = 0;
#pragma unroll
  for (int j = 0; j < 16; j++) {
    int b = top - 1 - j;
    cs[j] = g_fcnt[b]; fs[j] = g_fsum[b]; s += cs[j];
  }
  csum[t] = s;
  __syncthreads();
  for (int off = 1; off < 256; off <<= 1) {
    unsigned v = (t >= off) ? csum[t - off] : 0u;
    __syncthreads();
    csum[t] += v;
    __syncthreads();
  }
  unsigned long long run = (unsigned long long)csum[t] - s;
  double c = 0.0;
#pragma unroll
  for (int j = 0; j < 16; j++) {
    long long need = r - (long long)run;
    if (need <= 0) break;
    unsigned cnt = cs[j];
    if ((long long)cnt <= need) c += (double)fs[j];
    else if (cnt > 0u) c += (double)need * (double)fs[j] / (double)cnt;
    run += cnt;
  }
  red[t] = c;
  __syncthreads();
  for (int off = 128; off; off >>= 1) {
    if (t < off) red[t] += red[t + off];
    __syncthreads();
  }
  if (t == 0) {
    double total = g_pos_loss + g_sum_above + red[0];
    double denom = 2.0 * g_pos_w + 2.0 * (double)K;
    out[0] = (float)(total / denom / (double)BSZ);
  }
}

// ---------------------------------------------------------------
extern "C" void kernel_launch(void* const* d_in, const int* in_sizes, int n_in,
                              void* d_out, int out_size) {
  (void)in_sizes; (void)n_in; (void)out_size;
  const float4* pr = (const float4*)d_in[0];
  const float4* vm = (const float4*)d_in[1];
  const float4* wt = (const float4*)d_in[2];
  float* out = (float*)d_out;
  k_init<<<32, 256>>>();
  k_main<<<1184, 256>>>(pr, vm, wt);
  k_thresh<<<1, 256>>>();
  k_collect<<<1184, 256>>>();
  k_fine<<<296, 256>>>();
  k_final<<<1, 256>>>(out);
}

// round 2
// speedup vs baseline: 2.1109x; 2.1109x over previous
#include <cuda_runtime.h>
#include <cstdint>

#define BSZ 32
#define HWPIX 409600
#define NPIX 13107200
#define G8 1638400            // NPIX/8 (8 pixels per uint4 of bf16 codes)
#define HW8 51200             // HWPIX/8
#define HW4 102400            // HWPIX/4
#define NB1 8192              // coarse bins = bf16 code >> 3
#define NB2 4096              // fine bins (bf16 codes within bracket)
#define MARGIN 150000LL       // rank-margin for sampled bracket (~13 sigma)

// -------- device scratch (static: no allocations allowed) --------
__device__ uint4 g_scratch[G8];             // 8 bf16 row-loss codes per entry (26MB)
__device__ unsigned int g_hist[NB1];        // sampled coarse histogram
__device__ unsigned int g_fcnt[NB2];        // fine histogram counts
__device__ float        g_fsum[NB2];        // fine histogram value sums
__device__ double g_pos_loss;
__device__ double g_pos_w;
__device__ double g_sum_above;
__device__ unsigned int g_sumPos;
__device__ unsigned int g_cnt_above;
__device__ int g_blo, g_bhi, g_shift;
__device__ long long g_K;

__device__ __forceinline__ unsigned f2bf(float v) {
  // round-to-nearest-even float -> bf16 code (v >= 0 here)
  unsigned u = __float_as_uint(v);
  return (u + 0x7FFFu + ((u >> 16) & 1u)) >> 16;
}
__device__ __forceinline__ float bf2f(unsigned code) {
  return __uint_as_float(code << 16);
}

// ---------------------------------------------------------------
__global__ void k_init() {
  int t = blockIdx.x * blockDim.x + threadIdx.x;
  int n = gridDim.x * blockDim.x;
  for (int i = t; i < NB1; i += n) g_hist[i] = 0u;
  for (int i = t; i < NB2; i += n) { g_fcnt[i] = 0u; g_fsum[i] = 0.f; }
  if (t == 0) {
    g_pos_loss = 0.0; g_pos_w = 0.0; g_sum_above = 0.0;
    g_sumPos = 0u; g_cnt_above = 0u;
  }
}

// ---------------------------------------------------------------
// Main pass: 8 pixels per thread-iteration. Reads predict/vec_mask/weight
// (262MB), writes bf16 row-loss codes (26MB), accumulates positive sums,
// builds sampled (1/64) coarse histogram of negative losses.
__global__ void __launch_bounds__(256) k_main(const float4* __restrict__ pr,
                                              const float4* __restrict__ vm,
                                              const float4* __restrict__ wt) {
  __shared__ unsigned sh[NB1];
  for (int i = threadIdx.x; i < NB1; i += 256) sh[i] = 0u;
  __syncthreads();
  float pl = 0.f, pw = 0.f; unsigned np = 0u;
  int stride = gridDim.x * blockDim.x;
  for (int i = blockIdx.x * blockDim.x + threadIdx.x; i < G8; i += stride) {
    int b = i / HW8;
    int base = 2 * i + b * HW4;          // float4 idx, channel 0
    float4 p0a = pr[base],       p0b = pr[base + 1];
    float4 p1a = pr[base + HW4], p1b = pr[base + HW4 + 1];
    float4 t0a = vm[base],       t0b = vm[base + 1];
    float4 t1a = vm[base + HW4], t1b = vm[base + HW4 + 1];
    float4 wa = wt[2 * i], wb = wt[2 * i + 1];
    unsigned c[8];
    float P0[8] = {p0a.x,p0a.y,p0a.z,p0a.w, p0b.x,p0b.y,p0b.z,p0b.w};
    float P1[8] = {p1a.x,p1a.y,p1a.z,p1a.w, p1b.x,p1b.y,p1b.z,p1b.w};
    float T0[8] = {t0a.x,t0a.y,t0a.z,t0a.w, t0b.x,t0b.y,t0b.z,t0b.w};
    float T1[8] = {t1a.x,t1a.y,t1a.z,t1a.w, t1b.x,t1b.y,t1b.z,t1b.w};
    float W [8] = {wa.x,wa.y,wa.z,wa.w, wb.x,wb.y,wb.z,wb.w};
#pragma unroll
    for (int j = 0; j < 8; j++) {
      float d0 = P0[j] - T0[j], d1 = P1[j] - T1[j];
      float se = fmaf(d0, d0, d1 * d1);
      if (W[j] > 0.f) {
        pl = fmaf(se, W[j], pl); pw += W[j]; np++;
        c[j] = 0x8000u;
      } else {
        c[j] = f2bf(se);
      }
    }
    if (((i & 7) == 0) && !(c[0] & 0x8000u))
      atomicAdd(&sh[c[0] >> 3], 1u);     // sample every 64th pixel
    uint4 o;
    o.x = c[0] | (c[1] << 16);
    o.y = c[2] | (c[3] << 16);
    o.z = c[4] | (c[5] << 16);
    o.w = c[6] | (c[7] << 16);
    g_scratch[i] = o;
  }
  for (int o = 16; o; o >>= 1) {
    pl += __shfl_down_sync(0xffffffffu, pl, o);
    pw += __shfl_down_sync(0xffffffffu, pw, o);
    np += __shfl_down_sync(0xffffffffu, np, o);
  }
  if ((threadIdx.x & 31u) == 0u) {
    if (pl != 0.f) atomicAdd(&g_pos_loss, (double)pl);
    if (pw != 0.f) atomicAdd(&g_pos_w, (double)pw);
    if (np) atomicAdd(&g_sumPos, np);
  }
  __syncthreads();
  for (int i = threadIdx.x; i < NB1; i += 256) {
    unsigned cnt = sh[i];
    if (cnt) atomicAdd(&g_hist[i], cnt);
  }
}

// ---------------------------------------------------------------
// From sampled histogram find bracket [blo, bhi] of coarse bins that is
// guaranteed (with MARGIN rank slack) to contain the K-th largest negative.
__global__ void k_thresh() {
  __shared__ unsigned csum[256];
  __shared__ int s_blo, s_bhi;
  __shared__ long long sK;
  int t = threadIdx.x;
  if (t == 0) {
    long long sp = (long long)g_sumPos;
    long long K = 3 * sp;
    long long sn = (long long)NPIX - sp;
    if (K > sn) K = sn;
    sK = K; g_K = K;
    s_blo = 0; s_bhi = NB1;
  }
  __syncthreads();
  long long K = sK;
  int top = NB1 - 32 * t;
  unsigned cs[32]; unsigned s = 0;
#pragma unroll
  for (int j = 0; j < 32; j++) { cs[j] = g_hist[top - 1 - j]; s += cs[j]; }
  csum[t] = s;
  __syncthreads();
  for (int off = 1; off < 256; off <<= 1) {
    unsigned v = (t >= off) ? csum[t - off] : 0u;
    __syncthreads();
    csum[t] += v;
    __syncthreads();
  }
  unsigned long long run = (unsigned long long)csum[t] - s;
#pragma unroll
  for (int j = 0; j < 32; j++) {
    int b = top - 1 - j;
    long long above = (long long)run * 64;
    run += cs[j];
    long long atb = (long long)run * 64;
    if (atb >= K + MARGIN) atomicMax(&s_blo, b);
    if (above <= K - MARGIN) atomicMin(&s_bhi, b);
  }
  __syncthreads();
  if (t == 0) {
    int blo = s_blo, bhi = s_bhi;
    if (bhi >= NB1) bhi = NB1 - 1;
    if (bhi < blo) bhi = blo;
    long long range_codes = ((long long)(bhi - blo + 1)) << 3;  // bf16 codes in bracket
    int shift = 0;
    while ((range_codes >> shift) > NB2) shift++;
    g_blo = blo; g_bhi = bhi; g_shift = shift;
  }
}

// ---------------------------------------------------------------
// Fused pass over scratch: exact sum/count of values above the bracket,
// plus fine histogram (counts + sums) of bracket values, privatized in
// shared and flushed (nonzero bins only) at block end. No compaction,
// no single-address global atomics.
__global__ void __launch_bounds__(256) k_collect() {
  __shared__ unsigned scnt[NB2];
  __shared__ float ssum[NB2];
  for (int i = threadIdx.x; i < NB2; i += 256) { scnt[i] = 0u; ssum[i] = 0.f; }
  __syncthreads();
  int blo = g_blo, bhi = g_bhi, shift = g_shift;
  unsigned cbase = ((unsigned)blo) << 3;
  float sa = 0.f; unsigned ca = 0u;
  int stride = gridDim.x * blockDim.x;
  for (int i = blockIdx.x * blockDim.x + threadIdx.x; i < G8; i += stride) {
    uint4 v = g_scratch[i];
    unsigned word[4] = {v.x, v.y, v.z, v.w};
#pragma unroll
    for (int wv = 0; wv < 4; wv++) {
#pragma unroll
      for (int h = 0; h < 2; h++) {
        unsigned code = (word[wv] >> (16 * h)) & 0xFFFFu;
        if (!(code & 0x8000u)) {
          int cb = (int)(code >> 3);
          if (cb > bhi) { sa += bf2f(code); ca++; }
          else if (cb >= blo) {
            unsigned key = (code - cbase) >> shift;
            if (key >= NB2) key = NB2 - 1;
            atomicAdd(&scnt[key], 1u);
            atomicAdd(&ssum[key], bf2f(code));
          }
        }
      }
    }
  }
  for (int o = 16; o; o >>= 1) {
    sa += __shfl_down_sync(0xffffffffu, sa, o);
    ca += __shfl_down_sync(0xffffffffu, ca, o);
  }
  if ((threadIdx.x & 31u) == 0u) {
    if (sa != 0.f) atomicAdd(&g_sum_above, (double)sa);
    if (ca) atomicAdd(&g_cnt_above, ca);
  }
  __syncthreads();
  for (int i = threadIdx.x; i < NB2; i += 256) {
    unsigned c = scnt[i];
    if (c) { atomicAdd(&g_fcnt[i], c); atomicAdd(&g_fsum[i], ssum[i]); }
  }
}

// ---------------------------------------------------------------
// Scan fine histogram top-down, take top-r with bin-mean interpolation,
// finalize loss. 1 block, 256 threads.
__global__ void k_final(float* out) {
  __shared__ unsigned csum[256];
  __shared__ double red[256];
  int t = threadIdx.x;
  long long K = g_K;
  long long r = K - (long long)g_cnt_above;
  if (r < 0) r = 0;
  int top = NB2 - 16 * t;
  unsigned cs[16]; float fs[16]; unsigned s = 0;
#pragma unroll
  for (int j = 0; j < 16; j++) {
    int b = top - 1 - j;
    cs[j] = g_fcnt[b]; fs[j] = g_fsum[b]; s += cs[j];
  }
  csum[t] = s;
  __syncthreads();
  for (int off = 1; off < 256; off <<= 1) {
    unsigned v = (t >= off) ? csum[t - off] : 0u;
    __syncthreads();
    csum[t] += v;
    __syncthreads();
  }
  unsigned long long run = (unsigned long long)csum[t] - s;
  double c = 0.0;
#pragma unroll
  for (int j = 0; j < 16; j++) {
    long long need = r - (long long)run;
    if (need <= 0) break;
    unsigned cnt = cs[j];
    if ((long long)cnt <= need) c += (double)fs[j];
    else if (cnt > 0u) c += (double)need * (double)fs[j] / (double)cnt;
    run += cnt;
  }
  red[t] = c;
  __syncthreads();
  for (int off = 128; off; off >>= 1) {
    if (t < off) red[t] += red[t + off];
    __syncthreads();
  }
  if (t == 0) {
    double total = g_pos_loss + g_sum_above + red[0];
    double denom = 2.0 * g_pos_w + 2.0 * (double)K;
    out[0] = (float)(total / denom / (double)BSZ);
  }
}

// ---------------------------------------------------------------
extern "C" void kernel_launch(void* const* d_in, const int* in_sizes, int n_in,
                              void* d_out, int out_size) {
  (void)in_sizes; (void)n_in; (void)out_size;
  const float4* pr = (const float4*)d_in[0];
  const float4* vm = (const float4*)d_in[1];
  const float4* wt = (const float4*)d_in[2];
  float* out = (float*)d_out;
  k_init<<<32, 256>>>();
  k_main<<<1184, 256>>>(pr, vm, wt);
  k_thresh<<<1, 256>>>();
  k_collect<<<1184, 256>>>();
  k_final<<<1, 256>>>(out);
}

// round 4
// speedup vs baseline: 2.9465x; 1.3958x over previous
#include <cuda_runtime.h>
#include <cuda_bf16.h>
#include <cstdint>

#define BSZ 32
#define HWPIX 409600
#define NPIX 13107200
#define HW4 102400            // HWPIX/4 (float4 units per channel-plane)
#define NSCR (NPIX/4)         // u64 scratch entries (4 bf16 codes each)
#define NB1C 2048             // coarse bins = code >> 5
#define NB2 1024              // fine bins (bf16 codes within bracket)
#define MARGIN 150000LL       // rank-margin for sampled bracket

typedef unsigned long long u64;

// -------- device scratch (static: no allocations allowed) --------
__device__ __align__(16) u64 g_scratch[NSCR];   // 4 bf16 row-loss codes per entry (26MB)
__device__ unsigned int g_hist[NB1C];           // sampled coarse histogram
__device__ unsigned int g_fcnt[NB2];            // fine histogram counts
__device__ float        g_fsum[NB2];            // fine histogram value sums
__device__ double g_pos_loss;
__device__ double g_pos_w;
__device__ double g_sum_above;
__device__ unsigned int g_sumPos;
__device__ unsigned int g_cnt_above;
__device__ int g_blo, g_bhi, g_shift;
__device__ long long g_K;

// ---- packed f32x2 helpers ----
__device__ __forceinline__ u64 pk2(float a, float b) {
  u64 r; asm("mov.b64 %0, {%1, %2};" : "=l"(r) : "f"(a), "f"(b)); return r;
}
__device__ __forceinline__ void upk2(u64 v, float& a, float& b) {
  asm("mov.b64 {%0, %1}, %2;" : "=f"(a), "=f"(b) : "l"(v));
}
__device__ __forceinline__ u64 fma2(u64 a, u64 b, u64 c) {
  u64 d; asm("fma.rn.f32x2 %0, %1, %2, %3;" : "=l"(d) : "l"(a), "l"(b), "l"(c)); return d;
}
__device__ __forceinline__ u64 mul2(u64 a, u64 b) {
  u64 d; asm("mul.rn.f32x2 %0, %1, %2;" : "=l"(d) : "l"(a), "l"(b)); return d;
}
__device__ __forceinline__ u64 add2(u64 a, u64 b) {
  u64 d; asm("add.rn.f32x2 %0, %1, %2;" : "=l"(d) : "l"(a), "l"(b)); return d;
}
// pack two f32 -> bf16x2 word (lo = s0, hi = s1), round-to-nearest-even
__device__ __forceinline__ unsigned cvt_bf2(float s0, float s1) {
  unsigned w;
  asm("cvt.rn.satfinite.bf16x2.f32 %0, %1, %2;" : "=r"(w) : "f"(s1), "f"(s0));
  return w;
}
__device__ __forceinline__ float bf2f(unsigned code) {
  return __uint_as_float(code << 16);
}

// ---------------------------------------------------------------
__global__ void k_init() {
  int t = blockIdx.x * blockDim.x + threadIdx.x;
  int n = gridDim.x * blockDim.x;
  for (int i = t; i < NB1C; i += n) g_hist[i] = 0u;
  for (int i = t; i < NB2; i += n) { g_fcnt[i] = 0u; g_fsum[i] = 0.f; }
  if (t == 0) {
    g_pos_loss = 0.0; g_pos_w = 0.0; g_sum_above = 0.0;
    g_sumPos = 0u; g_cnt_above = 0u;
  }
}

// ---------------------------------------------------------------
// Main pass. blockIdx.y = batch. Reads predict/vec_mask/weight (262MB),
// writes packed bf16 row-loss codes (26MB, positives encoded as code 0),
// accumulates positive sums, sampled (1/64) coarse histogram.
__global__ void __launch_bounds__(256) k_main(const float4* __restrict__ pr,
                                              const float4* __restrict__ vm,
                                              const float4* __restrict__ wt) {
  __shared__ unsigned sh[NB1C];
  for (int i = threadIdx.x; i < NB1C; i += 256) sh[i] = 0u;
  __syncthreads();
  const int b = blockIdx.y;
  const float4* prb = pr + (size_t)b * 2 * HW4;
  const float4* vmb = vm + (size_t)b * 2 * HW4;
  const float4* wtb = wt + (size_t)b * HW4;
  u64* scr = g_scratch + (size_t)b * HW4;
  const u64 M1 = pk2(-1.f, -1.f);
  u64 pl = 0ull, pw = 0ull;       // packed f32x2 accumulators (bits 0 == (0,0))
  unsigned np = 0u;
  const int stride = gridDim.x * blockDim.x;
  for (int u = blockIdx.x * blockDim.x + threadIdx.x; u < HW4; u += stride) {
    float4 p0 = prb[u], p1 = prb[u + HW4];
    float4 t0 = vmb[u], t1 = vmb[u + HW4];
    float4 w = wtb[u];
    // pair A (.x,.y)
    u64 d0 = fma2(pk2(t0.x, t0.y), M1, pk2(p0.x, p0.y));
    u64 d1 = fma2(pk2(t1.x, t1.y), M1, pk2(p1.x, p1.y));
    u64 se = fma2(d1, d1, mul2(d0, d0));
    u64 wA = pk2(w.x, w.y);
    pl = fma2(se, wA, pl);
    pw = add2(pw, wA);
    float s0, s1; upk2(se, s0, s1);
    unsigned wordA = cvt_bf2(s0, s1);
    if (w.x > 0.f) { wordA &= 0xFFFF0000u; np++; }
    if (w.y > 0.f) { wordA &= 0x0000FFFFu; np++; }
    // pair B (.z,.w)
    u64 e0 = fma2(pk2(t0.z, t0.w), M1, pk2(p0.z, p0.w));
    u64 e1 = fma2(pk2(t1.z, t1.w), M1, pk2(p1.z, p1.w));
    u64 sf = fma2(e1, e1, mul2(e0, e0));
    u64 wB = pk2(w.z, w.w);
    pl = fma2(sf, wB, pl);
    pw = add2(pw, wB);
    float s2, s3; upk2(sf, s2, s3);
    unsigned wordB = cvt_bf2(s2, s3);
    if (w.z > 0.f) { wordB &= 0xFFFF0000u; np++; }
    if (w.w > 0.f) { wordB &= 0x0000FFFFu; np++; }
    if ((u & 15) == 0)                      // every 64th pixel
      atomicAdd(&sh[(wordA & 0xFFFFu) >> 5], 1u);
    scr[u] = (u64)wordA | ((u64)wordB << 32);
  }
  float pl0, pl1, pw0, pw1;
  upk2(pl, pl0, pl1); upk2(pw, pw0, pw1);
  float plf = pl0 + pl1, pwf = pw0 + pw1;
  for (int o = 16; o; o >>= 1) {
    plf += __shfl_down_sync(0xffffffffu, plf, o);
    pwf += __shfl_down_sync(0xffffffffu, pwf, o);
    np  += __shfl_down_sync(0xffffffffu, np, o);
  }
  if ((threadIdx.x & 31u) == 0u) {
    if (plf != 0.f) atomicAdd(&g_pos_loss, (double)plf);
    if (pwf != 0.f) atomicAdd(&g_pos_w, (double)pwf);
    if (np) atomicAdd(&g_sumPos, np);
  }
  __syncthreads();
  for (int i = threadIdx.x; i < NB1C; i += 256) {
    unsigned cnt = sh[i];
    if (cnt) atomicAdd(&g_hist[i], cnt);
  }
}

// ---------------------------------------------------------------
// Bracket [blo, bhi] of coarse bins (32 codes each) guaranteed (with
// MARGIN rank slack) to contain the K-th largest negative.
__global__ void k_thresh() {
  __shared__ unsigned csum[256];
  __shared__ int s_blo, s_bhi;
  __shared__ long long sK;
  int t = threadIdx.x;
  if (t == 0) {
    long long sp = (long long)g_sumPos;
    long long K = 3 * sp;
    long long sn = (long long)NPIX - sp;
    if (K > sn) K = sn;
    sK = K; g_K = K;
    s_blo = 0; s_bhi = NB1C;
  }
  __syncthreads();
  long long K = sK;
  int top = NB1C - 8 * t;
  unsigned cs[8]; unsigned s = 0;
#pragma unroll
  for (int j = 0; j < 8; j++) { cs[j] = g_hist[top - 1 - j]; s += cs[j]; }
  csum[t] = s;
  __syncthreads();
  for (int off = 1; off < 256; off <<= 1) {
    unsigned v = (t >= off) ? csum[t - off] : 0u;
    __syncthreads();
    csum[t] += v;
    __syncthreads();
  }
  unsigned long long run = (unsigned long long)csum[t] - s;
#pragma unroll
  for (int j = 0; j < 8; j++) {
    int bn = top - 1 - j;
    long long above = (long long)run * 64;
    run += cs[j];
    long long atb = (long long)run * 64;
    if (atb >= K + MARGIN) atomicMax(&s_blo, bn);
    if (above <= K - MARGIN) atomicMin(&s_bhi, bn);
  }
  __syncthreads();
  if (t == 0) {
    int blo = s_blo, bhi = s_bhi;
    if (bhi >= NB1C) bhi = NB1C - 1;
    if (bhi < blo) bhi = blo;
    long long range_codes = ((long long)(bhi - blo + 1)) << 5;
    int shift = 0;
    while ((range_codes >> shift) > NB2) shift++;
    g_blo = blo; g_bhi = bhi; g_shift = shift;
  }
}

// ---------------------------------------------------------------
// Scan scratch: exact sum/count above bracket + fine histogram of bracket
// values. All codes are 15-bit (positives stored as 0), so per-word
// "any half >= lo" is a carry-trick add + mask.
__global__ void __launch_bounds__(256) k_collect() {
  __shared__ unsigned scnt[NB2];
  __shared__ float ssum[NB2];
  for (int i = threadIdx.x; i < NB2; i += 256) { scnt[i] = 0u; ssum[i] = 0.f; }
  __syncthreads();
  const int blo = g_blo, bhi = g_bhi, shift = g_shift;
  const unsigned lo_code = ((unsigned)blo) << 5;
  const unsigned hi_code = ((unsigned)(bhi + 1)) << 5;   // codes >= hi_code are "above"
  unsigned addk = 0x8000u - lo_code;
  addk |= addk << 16;
  float sa = 0.f; unsigned ca = 0u;
  const ulonglong2* s2 = (const ulonglong2*)g_scratch;
  const int nit = NSCR / 4;                 // 16 pixels per iteration
  const int stride = gridDim.x * blockDim.x;
  for (int i = blockIdx.x * blockDim.x + threadIdx.x; i < nit; i += stride) {
    ulonglong2 va = s2[2 * i];
    ulonglong2 vb = s2[2 * i + 1];
    u64 qs[4] = {va.x, va.y, vb.x, vb.y};
#pragma unroll
    for (int q = 0; q < 4; q++) {
      unsigned wl = (unsigned)qs[q];
      unsigned wh = (unsigned)(qs[q] >> 32);
#pragma unroll
      for (int k = 0; k < 2; k++) {
        unsigned wrd = k ? wh : wl;
        if (((wrd + addk) & 0x80008000u) != 0u) {
          unsigned h0 = wrd & 0xFFFFu;
          unsigned h1 = wrd >> 16;
          if (h0 >= hi_code) { sa += bf2f(h0); ca++; }
          else if (h0 >= lo_code) {
            unsigned key = (h0 - lo_code) >> shift;
            if (key >= NB2) key = NB2 - 1;
            atomicAdd(&scnt[key], 1u); atomicAdd(&ssum[key], bf2f(h0));
          }
          if (h1 >= hi_code) { sa += bf2f(h1); ca++; }
          else if (h1 >= lo_code) {
            unsigned key = (h1 - lo_code) >> shift;
            if (key >= NB2) key = NB2 - 1;
            atomicAdd(&scnt[key], 1u); atomicAdd(&ssum[key], bf2f(h1));
          }
        }
      }
    }
  }
  for (int o = 16; o; o >>= 1) {
    sa += __shfl_down_sync(0xffffffffu, sa, o);
    ca += __shfl_down_sync(0xffffffffu, ca, o);
  }
  if ((threadIdx.x & 31u) == 0u) {
    if (sa != 0.f) atomicAdd(&g_sum_above, (double)sa);
    if (ca) atomicAdd(&g_cnt_above, ca);
  }
  __syncthreads();
  for (int i = threadIdx.x; i < NB2; i += 256) {
    unsigned c = scnt[i];
    if (c) { atomicAdd(&g_fcnt[i], c); atomicAdd(&g_fsum[i], ssum[i]); }
  }
}

// ---------------------------------------------------------------
// Top-down scan of fine histogram; take top-r with bin-mean interpolation
// in the boundary bin; finalize loss.
__global__ void k_final(float* out) {
  __shared__ unsigned csum[256];
  __shared__ double red[256];
  int t = threadIdx.x;
  long long K = g_K;
  long long r = K - (long long)g_cnt_above;
  if (r < 0) r = 0;
  int top = NB2 - 4 * t;
  unsigned cs[4]; float fs[4]; unsigned s = 0;
#pragma unroll
  for (int j = 0; j < 4; j++) {
    int bn = top - 1 - j;
    cs[j] = g_fcnt[bn]; fs[j] = g_fsum[bn]; s += cs[j];
  }
  csum[t] = s;
  __syncthreads();
  for (int off = 1; off < 256; off <<= 1) {
    unsigned v = (t >= off) ? csum[t - off] : 0u;
    __syncthreads();
    csum[t] += v;
    __syncthreads();
  }
  unsigned long long run = (unsigned long long)csum[t] - s;
  double c = 0.0;
#pragma unroll
  for (int j = 0; j < 4; j++) {
    long long need = r - (long long)run;
    if (need <= 0) break;
    unsigned cnt = cs[j];
    if ((long long)cnt <= need) c += (double)fs[j];
    else if (cnt > 0u) c += (double)need * (double)fs[j] / (double)cnt;
    run += cnt;
  }
  red[t] = c;
  __syncthreads();
  for (int off = 128; off; off >>= 1) {
    if (t < off) red[t] += red[t + off];
    __syncthreads();
  }
  if (t == 0) {
    double total = g_pos_loss + g_sum_above + red[0];
    double denom = 2.0 * g_pos_w + 2.0 * (double)K;
    out[0] = (float)(total / denom / (double)BSZ);
  }
}

// ---------------------------------------------------------------
extern "C" void kernel_launch(void* const* d_in, const int* in_sizes, int n_in,
                              void* d_out, int out_size) {
  (void)in_sizes; (void)n_in; (void)out_size;
  const float4* pr = (const float4*)d_in[0];
  const float4* vm = (const float4*)d_in[1];
  const float4* wt = (const float4*)d_in[2];
  float* out = (float*)d_out;
  k_init<<<8, 256>>>();
  k_main<<<dim3(37, BSZ), 256>>>(pr, vm, wt);
  k_thresh<<<1, 256>>>();
  k_collect<<<1184, 256>>>();
  k_final<<<1, 256>>>(out);
}

// round 5
// speedup vs baseline: 3.5972x; 1.2208x over previous
#include <cuda_runtime.h>
#include <cuda_bf16.h>
#include <cstdint>

#define BSZ 32
#define HWPIX 409600
#define NPIX 13107200
#define HW4 102400            // float4 units per channel-plane (u64 scratch units per batch)
#define HW8 51200             // 8-pixel chunks per batch
#define NSCR (NPIX/4)         // u64 scratch entries (4 bf16 codes each)
#define NB1C 2048             // coarse bins = code >> 5
#define NB2 1024              // fine bins (bf16 codes within bracket)
#define MARGIN 100000LL       // rank-margin for sampled bracket (~9 sigma)
#define CT 409600             // k_collect total threads (NPIX/32)

typedef unsigned long long u64;

// -------- device scratch (static; zero-initialized at module load; ------
// -------- k_final re-zeros everything it consumed => self-cleaning) -----
__device__ __align__(16) u64 g_scratch[NSCR];   // 4 bf16 row-loss codes per entry (26MB)
__device__ unsigned int g_hist[NB1C];           // sampled coarse histogram
__device__ unsigned int g_fcnt[NB2];            // fine histogram counts
__device__ float        g_fsum[NB2];            // fine histogram value sums
__device__ double g_pos_loss;
__device__ double g_pos_w;
__device__ double g_sum_above;
__device__ unsigned int g_sumPos;
__device__ unsigned int g_cnt_above;
__device__ int g_blo, g_bhi, g_shift;
__device__ long long g_K;

// ---- packed f32x2 helpers ----
__device__ __forceinline__ u64 pk2(float a, float b) {
  u64 r; asm("mov.b64 %0, {%1, %2};" : "=l"(r) : "f"(a), "f"(b)); return r;
}
__device__ __forceinline__ void upk2(u64 v, float& a, float& b) {
  asm("mov.b64 {%0, %1}, %2;" : "=f"(a), "=f"(b) : "l"(v));
}
__device__ __forceinline__ u64 fma2(u64 a, u64 b, u64 c) {
  u64 d; asm("fma.rn.f32x2 %0, %1, %2, %3;" : "=l"(d) : "l"(a), "l"(b), "l"(c)); return d;
}
__device__ __forceinline__ u64 mul2(u64 a, u64 b) {
  u64 d; asm("mul.rn.f32x2 %0, %1, %2;" : "=l"(d) : "l"(a), "l"(b)); return d;
}
__device__ __forceinline__ u64 add2(u64 a, u64 b) {
  u64 d; asm("add.rn.f32x2 %0, %1, %2;" : "=l"(d) : "l"(a), "l"(b)); return d;
}
// pack two f32 -> bf16x2 word (lo = s0, hi = s1), round-to-nearest-even
__device__ __forceinline__ unsigned cvt_bf2(float s0, float s1) {
  unsigned w;
  asm("cvt.rn.satfinite.bf16x2.f32 %0, %1, %2;" : "=r"(w) : "f"(s1), "f"(s0));
  return w;
}
__device__ __forceinline__ float bf2f(unsigned code) {
  return __uint_as_float(code << 16);
}

// ---------------------------------------------------------------
// Main pass. One 8-pixel chunk per thread (grid exactly covers data).
// blockIdx.y = batch. Reads predict/vec_mask/weight (262MB, 10 batched
// LDG.128), writes packed bf16 row-loss codes (26MB, 1 STG.128, positives
// encoded as code 0), block-reduced positive sums, sampled coarse hist.
__global__ void __launch_bounds__(256) k_main(const float4* __restrict__ pr,
                                              const float4* __restrict__ vm,
                                              const float4* __restrict__ wt) {
  __shared__ unsigned sh[NB1C];
  __shared__ float r_pl[8], r_pw[8];
  __shared__ unsigned r_np[8];
  for (int i = threadIdx.x; i < NB1C; i += 256) sh[i] = 0u;
  __syncthreads();
  const int b = blockIdx.y;
  const int i = blockIdx.x * 256 + threadIdx.x;     // [0, HW8)
  const int base = 2 * i;
  const float4* prb = pr + (size_t)b * 2 * HW4;
  const float4* vmb = vm + (size_t)b * 2 * HW4;
  const float4* wtb = wt + (size_t)b * HW4;
  // 10 independent loads (front-batched by ptxas)
  float4 p0a = prb[base],       p0b = prb[base + 1];
  float4 p1a = prb[base + HW4], p1b = prb[base + HW4 + 1];
  float4 t0a = vmb[base],       t0b = vmb[base + 1];
  float4 t1a = vmb[base + HW4], t1b = vmb[base + HW4 + 1];
  float4 wa = wtb[base], wb = wtb[base + 1];
  const u64 M1 = pk2(-1.f, -1.f);
  u64 pl = 0ull, pw = 0ull;
  unsigned np = 0u;
  // --- group a, pair (px0, px1) ---
  u64 d0 = fma2(pk2(t0a.x, t0a.y), M1, pk2(p0a.x, p0a.y));
  u64 d1 = fma2(pk2(t1a.x, t1a.y), M1, pk2(p1a.x, p1a.y));
  u64 se = fma2(d1, d1, mul2(d0, d0));
  u64 wv = pk2(wa.x, wa.y);
  pl = fma2(se, wv, pl); pw = add2(pw, wv);
  float s0, s1; upk2(se, s0, s1);
  unsigned wA = cvt_bf2(s0, s1);
  if (wa.x > 0.f) { wA &= 0xFFFF0000u; np++; }
  if (wa.y > 0.f) { wA &= 0x0000FFFFu; np++; }
  // --- group a, pair (px2, px3) ---
  d0 = fma2(pk2(t0a.z, t0a.w), M1, pk2(p0a.z, p0a.w));
  d1 = fma2(pk2(t1a.z, t1a.w), M1, pk2(p1a.z, p1a.w));
  se = fma2(d1, d1, mul2(d0, d0));
  wv = pk2(wa.z, wa.w);
  pl = fma2(se, wv, pl); pw = add2(pw, wv);
  upk2(se, s0, s1);
  unsigned wB = cvt_bf2(s0, s1);
  if (wa.z > 0.f) { wB &= 0xFFFF0000u; np++; }
  if (wa.w > 0.f) { wB &= 0x0000FFFFu; np++; }
  // --- group b, pair (px4, px5) ---
  d0 = fma2(pk2(t0b.x, t0b.y), M1, pk2(p0b.x, p0b.y));
  d1 = fma2(pk2(t1b.x, t1b.y), M1, pk2(p1b.x, p1b.y));
  se = fma2(d1, d1, mul2(d0, d0));
  wv = pk2(wb.x, wb.y);
  pl = fma2(se, wv, pl); pw = add2(pw, wv);
  upk2(se, s0, s1);
  unsigned wC = cvt_bf2(s0, s1);
  if (wb.x > 0.f) { wC &= 0xFFFF0000u; np++; }
  if (wb.y > 0.f) { wC &= 0x0000FFFFu; np++; }
  // --- group b, pair (px6, px7) ---
  d0 = fma2(pk2(t0b.z, t0b.w), M1, pk2(p0b.z, p0b.w));
  d1 = fma2(pk2(t1b.z, t1b.w), M1, pk2(p1b.z, p1b.w));
  se = fma2(d1, d1, mul2(d0, d0));
  wv = pk2(wb.z, wb.w);
  pl = fma2(se, wv, pl); pw = add2(pw, wv);
  upk2(se, s0, s1);
  unsigned wD = cvt_bf2(s0, s1);
  if (wb.z > 0.f) { wD &= 0xFFFF0000u; np++; }
  if (wb.w > 0.f) { wD &= 0x0000FFFFu; np++; }

  if ((i & 7) == 0)                      // every 64th pixel (bin0 noise is harmless)
    atomicAdd(&sh[(wA & 0xFFFFu) >> 5], 1u);
  ulonglong2* s2b = (ulonglong2*)(g_scratch + (size_t)b * HW4);
  ulonglong2 outv;
  outv.x = (u64)wA | ((u64)wB << 32);
  outv.y = (u64)wC | ((u64)wD << 32);
  s2b[i] = outv;

  // block reduction of positive sums
  float pl0, pl1, pw0, pw1;
  upk2(pl, pl0, pl1); upk2(pw, pw0, pw1);
  float plf = pl0 + pl1, pwf = pw0 + pw1;
  for (int o = 16; o; o >>= 1) {
    plf += __shfl_down_sync(0xffffffffu, plf, o);
    pwf += __shfl_down_sync(0xffffffffu, pwf, o);
    np  += __shfl_down_sync(0xffffffffu, np, o);
  }
  int wid = threadIdx.x >> 5;
  if ((threadIdx.x & 31u) == 0u) { r_pl[wid] = plf; r_pw[wid] = pwf; r_np[wid] = np; }
  __syncthreads();
  if (threadIdx.x == 0) {
    float bpl = 0.f, bpw = 0.f; unsigned bnp = 0u;
#pragma unroll
    for (int k = 0; k < 8; k++) { bpl += r_pl[k]; bpw += r_pw[k]; bnp += r_np[k]; }
    if (bpl != 0.f) atomicAdd(&g_pos_loss, (double)bpl);
    if (bpw != 0.f) atomicAdd(&g_pos_w, (double)bpw);
    if (bnp) atomicAdd(&g_sumPos, bnp);
  }
  // flush sampled histogram
  for (int k = threadIdx.x; k < NB1C; k += 256) {
    unsigned cnt = sh[k];
    if (cnt) atomicAdd(&g_hist[k], cnt);
  }
}

// ---------------------------------------------------------------
// Bracket [blo, bhi] of coarse bins (32 codes each) guaranteed (with
// MARGIN rank slack) to contain the K-th largest negative.
__global__ void k_thresh() {
  __shared__ unsigned csum[256];
  __shared__ int s_blo, s_bhi;
  __shared__ long long sK;
  int t = threadIdx.x;
  if (t == 0) {
    long long sp = (long long)g_sumPos;
    long long K = 3 * sp;
    long long sn = (long long)NPIX - sp;
    if (K > sn) K = sn;
    sK = K; g_K = K;
    s_blo = 0; s_bhi = NB1C;
  }
  __syncthreads();
  long long K = sK;
  int top = NB1C - 8 * t;
  unsigned cs[8]; unsigned s = 0;
#pragma unroll
  for (int j = 0; j < 8; j++) { cs[j] = g_hist[top - 1 - j]; s += cs[j]; }
  csum[t] = s;
  __syncthreads();
  for (int off = 1; off < 256; off <<= 1) {
    unsigned v = (t >= off) ? csum[t - off] : 0u;
    __syncthreads();
    csum[t] += v;
    __syncthreads();
  }
  unsigned long long run = (unsigned long long)csum[t] - s;
#pragma unroll
  for (int j = 0; j < 8; j++) {
    int bn = top - 1 - j;
    long long above = (long long)run * 64;
    run += cs[j];
    long long atb = (long long)run * 64;
    if (atb >= K + MARGIN) atomicMax(&s_blo, bn);
    if (above <= K - MARGIN) atomicMin(&s_bhi, bn);
  }
  __syncthreads();
  if (t == 0) {
    int blo = s_blo, bhi = s_bhi;
    if (bhi >= NB1C) bhi = NB1C - 1;
    if (bhi < blo) bhi = blo;
    long long range_codes = ((long long)(bhi - blo + 1)) << 5;
    int shift = 0;
    while ((range_codes >> shift) > NB2) shift++;
    g_blo = blo; g_bhi = bhi; g_shift = shift;
  }
}

// ---------------------------------------------------------------
// Scan scratch: exact sum/count above bracket + fine histogram of bracket
// values. One thread per 32 pixels: 4 front-batched LDG.128, no loop.
// Codes are 15-bit (positives stored as 0): per-word skip test is a
// carry-trick add + mask.
__global__ void __launch_bounds__(256) k_collect() {
  __shared__ unsigned scnt[NB2];
  __shared__ float ssum[NB2];
  for (int i = threadIdx.x; i < NB2; i += 256) { scnt[i] = 0u; ssum[i] = 0.f; }
  __syncthreads();
  const int blo = g_blo, bhi = g_bhi, shift = g_shift;
  const unsigned lo_code = ((unsigned)blo) << 5;
  const unsigned hi_code = ((unsigned)(bhi + 1)) << 5;
  unsigned addk = 0x8000u - lo_code;
  addk |= addk << 16;
  const int tid = blockIdx.x * 256 + threadIdx.x;     // [0, CT)
  const ulonglong2* s2 = (const ulonglong2*)g_scratch;
  // 4 independent strided loads (front-batched, fully coalesced)
  ulonglong2 v0 = s2[tid];
  ulonglong2 v1 = s2[tid + CT];
  ulonglong2 v2 = s2[tid + 2 * CT];
  ulonglong2 v3 = s2[tid + 3 * CT];
  u64 q[8] = {v0.x, v0.y, v1.x, v1.y, v2.x, v2.y, v3.x, v3.y};
  float sa = 0.f; unsigned ca = 0u;
#pragma unroll
  for (int j = 0; j < 8; j++) {
    unsigned wl = (unsigned)q[j];
    unsigned wh = (unsigned)(q[j] >> 32);
#pragma unroll
    for (int k = 0; k < 2; k++) {
      unsigned wrd = k ? wh : wl;
      if (((wrd + addk) & 0x80008000u) != 0u) {
        unsigned h0 = wrd & 0xFFFFu;
        unsigned h1 = wrd >> 16;
        if (h0 >= hi_code) { sa += bf2f(h0); ca++; }
        else if (h0 >= lo_code) {
          unsigned key = (h0 - lo_code) >> shift;
          if (key >= NB2) key = NB2 - 1;
          atomicAdd(&scnt[key], 1u); atomicAdd(&ssum[key], bf2f(h0));
        }
        if (h1 >= hi_code) { sa += bf2f(h1); ca++; }
        else if (h1 >= lo_code) {
          unsigned key = (h1 - lo_code) >> shift;
          if (key >= NB2) key = NB2 - 1;
          atomicAdd(&scnt[key], 1u); atomicAdd(&ssum[key], bf2f(h1));
        }
      }
    }
  }
  for (int o = 16; o; o >>= 1) {
    sa += __shfl_down_sync(0xffffffffu, sa, o);
    ca += __shfl_down_sync(0xffffffffu, ca, o);
  }
  __shared__ float r_sa[8];
  __shared__ unsigned r_ca[8];
  int wid = threadIdx.x >> 5;
  if ((threadIdx.x & 31u) == 0u) { r_sa[wid] = sa; r_ca[wid] = ca; }
  __syncthreads();
  if (threadIdx.x == 0) {
    float bs = 0.f; unsigned bc = 0u;
#pragma unroll
    for (int k = 0; k < 8; k++) { bs += r_sa[k]; bc += r_ca[k]; }
    if (bs != 0.f) atomicAdd(&g_sum_above, (double)bs);
    if (bc) atomicAdd(&g_cnt_above, bc);
  }
  for (int i = threadIdx.x; i < NB2; i += 256) {
    unsigned c = scnt[i];
    if (c) { atomicAdd(&g_fcnt[i], c); atomicAdd(&g_fsum[i], ssum[i]); }
  }
}

// ---------------------------------------------------------------
// Top-down scan of fine histogram; take top-r with bin-mean interpolation
// in the boundary bin; finalize loss; then re-zero all global state so the
// next (graph-replayed) launch sequence starts clean.
__global__ void k_final(float* out) {
  __shared__ unsigned csum[256];
  __shared__ double red[256];
  int t = threadIdx.x;
  long long K = g_K;
  long long r = K - (long long)g_cnt_above;
  if (r < 0) r = 0;
  int top = NB2 - 4 * t;
  unsigned cs[4]; float fs[4]; unsigned s = 0;
#pragma unroll
  for (int j = 0; j < 4; j++) {
    int bn = top - 1 - j;
    cs[j] = g_fcnt[bn]; fs[j] = g_fsum[bn]; s += cs[j];
  }
  csum[t] = s;
  __syncthreads();
  for (int off = 1; off < 256; off <<= 1) {
    unsigned v = (t >= off) ? csum[t - off] : 0u;
    __syncthreads();
    csum[t] += v;
    __syncthreads();
  }
  unsigned long long run = (unsigned long long)csum[t] - s;
  double c = 0.0;
#pragma unroll
  for (int j = 0; j < 4; j++) {
    long long need = r - (long long)run;
    if (need <= 0) break;
    unsigned cnt = cs[j];
    if ((long long)cnt <= need) c += (double)fs[j];
    else if (cnt > 0u) c += (double)need * (double)fs[j] / (double)cnt;
    run += cnt;
  }
  red[t] = c;
  __syncthreads();
  for (int off = 128; off; off >>= 1) {
    if (t < off) red[t] += red[t + off];
    __syncthreads();
  }
  if (t == 0) {
    double total = g_pos_loss + g_sum_above + red[0];
    double denom = 2.0 * g_pos_w + 2.0 * (double)K;
    out[0] = (float)(total / denom / (double)BSZ);
  }
  __syncthreads();
  // ---- self-clean for the next replay ----
  for (int i = t; i < NB1C; i += 256) g_hist[i] = 0u;
  for (int i = t; i < NB2; i += 256) { g_fcnt[i] = 0u; g_fsum[i] = 0.f; }
  if (t == 0) {
    g_pos_loss = 0.0; g_pos_w = 0.0; g_sum_above = 0.0;
    g_sumPos = 0u; g_cnt_above = 0u;
  }
}

// ---------------------------------------------------------------
extern "C" void kernel_launch(void* const* d_in, const int* in_sizes, int n_in,
                              void* d_out, int out_size) {
  (void)in_sizes; (void)n_in; (void)out_size;
  const float4* pr = (const float4*)d_in[0];
  const float4* vm = (const float4*)d_in[1];
  const float4* wt = (const float4*)d_in[2];
  float* out = (float*)d_out;
  k_main<<<dim3(HW8 / 256, BSZ), 256>>>(pr, vm, wt);
  k_thresh<<<1, 256>>>();
  k_collect<<<CT / 256, 256>>>();
  k_final<<<1, 256>>>(out);
}